// round 4
// baseline (speedup 1.0000x reference)
#include <cuda_runtime.h>

#define NCTA 128
#define NTHR 256
#define BB   64      // batch
#define TT   512     // timesteps
#define DIN  64      // input dim
#define HH   512     // hidden
#define HP   576     // per-batch smem pitch (floats): 16 slices x 36
#define RP   68      // red pitch

// Persistent state (device globals; no cudaMalloc allowed)
__device__ float    g_h1[2][BB * HH];
__device__ float    g_h2[2][BB * HH];
__device__ unsigned g_bar;

typedef unsigned long long ull;

__device__ __forceinline__ float sigm(float x)      { return 1.f / (1.f + __expf(-x)); }
__device__ __forceinline__ float tanh_fast(float x) { return 2.f / (1.f + __expf(-2.f * x)) - 1.f; }

__device__ __forceinline__ ull f2(ull a, ull b, ull c) {
    ull d;
    asm("fma.rn.f32x2 %0, %1, %2, %3;" : "=l"(d) : "l"(a), "l"(b), "l"(c));
    return d;
}
__device__ __forceinline__ ull packf2(float x, float y) {
    return (ull)__float_as_uint(x) | ((ull)__float_as_uint(y) << 32);
}
__device__ __forceinline__ float f2lo(ull a) { return __uint_as_float((unsigned)a); }
__device__ __forceinline__ float f2hi(ull a) { return __uint_as_float((unsigned)(a >> 32)); }

__global__ void init_kernel() {
    unsigned i = blockIdx.x * blockDim.x + threadIdx.x;
    if (i == 0) g_bar = 0u;
    if (i < BB * HH) { g_h1[0][i] = 0.f; g_h2[0][i] = 0.f; }
}

// Monotonic-target grid barrier (counter reset by init_kernel each launch).
// __threadfence (gpu scope) also flushes this SM's L1D (CCTL.IVALL), so
// post-barrier plain loads of peer-written h are coherent.
__device__ __forceinline__ void gbar(unsigned target) {
    __syncthreads();
    if (threadIdx.x == 0) {
        __threadfence();
        atomicAdd(&g_bar, 1u);
        while (*((volatile unsigned*)&g_bar) < target) { }
        __threadfence();
    }
    __syncthreads();
}

__global__ void __launch_bounds__(NTHR, 1) lstm_kernel(
    const float* __restrict__ x,
    const float* __restrict__ Wih0, const float* __restrict__ Whh0,
    const float* __restrict__ bih0, const float* __restrict__ bhh0,
    const float* __restrict__ Wih1, const float* __restrict__ Whh1,
    const float* __restrict__ bih1, const float* __restrict__ bhh1,
    const float* __restrict__ fcw,  const float* __restrict__ fcb,
    float* __restrict__ out)
{
    extern __shared__ float sm[];        // h area: BB*HP floats, then red: 16*RP
    float* red = sm + BB * HP;

    const int tid = threadIdx.x;
    const int cta = blockIdx.x;
    const int r   = tid >> 4;            // gate-row within CTA (0..15)
    const int s   = tid & 15;            // K-slice (0..15)
    const int u   = r >> 2;              // unit-local
    const int g   = r & 3;               // gate (i,f,g,o)
    const int grow = g * HH + cta * 4 + u;

    // ---- Register-resident weights for the whole run ----
    // L0: concat K = [h1(512) | x(64)] = 576; slice = 36 floats (18 f32x2 pairs)
    ull w0[18], w1a[16], w1b[16];
#pragma unroll
    for (int j = 0; j < 18; ++j) {
        int k = s * 36 + 2 * j;
        float f0 = (k     < HH) ? Whh0[grow * HH + k]     : Wih0[grow * DIN + (k - HH)];
        float f1 = (k + 1 < HH) ? Whh0[grow * HH + k + 1] : Wih0[grow * DIN + (k + 1 - HH)];
        w0[j] = packf2(f0, f1);
    }
#pragma unroll
    for (int j = 0; j < 16; ++j) {
        int k = s * 32 + 2 * j;
        w1a[j] = packf2(Wih1[grow * HH + k], Wih1[grow * HH + k + 1]);
        w1b[j] = packf2(Whh1[grow * HH + k], Whh1[grow * HH + k + 1]);
    }

    // Epilogue mapping: 4 units x 64 batches
    const int eb = tid & 63;
    const int eu = tid >> 6;
    const int ej = cta * 4 + eu;
    float bias0[4], bias1[4];
#pragma unroll
    for (int gg = 0; gg < 4; ++gg) {
        bias0[gg] = bih0[gg * HH + ej] + bhh0[gg * HH + ej];
        bias1[gg] = bih1[gg * HH + ej] + bhh1[gg * HH + ej];
    }

    float c1 = 0.f, c2 = 0.f;
    unsigned bi = 0;

    for (int t = 0; t < TT; ++t) {
        const int p = t & 1;

        // ======== stage L0 input: [h1[p] | x_t] contiguous, pitch HP ========
        __syncthreads();
        {
            const float4* hsrc = (const float4*)g_h1[p];
            for (int idx = tid; idx < BB * 144; idx += NTHR) {
                int b = idx / 144;
                int q = idx - b * 144;
                float4 v;
                if (q < 128) v = hsrc[b * 128 + q];
                else         v = *(const float4*)&x[(b * TT + t) * DIN + (q - 128) * 4];
                *(float4*)(sm + b * HP + q * 4) = v;
            }
        }
        __syncthreads();

        // ======== compute L0 gates ========
#pragma unroll 2
        for (int b = 0; b < BB; ++b) {
            const ulonglong2* hp = (const ulonglong2*)(sm + b * HP + s * 36);
            ull a = 0ull;
#pragma unroll
            for (int j = 0; j < 9; ++j) {
                ulonglong2 hv = hp[j];
                a = f2(w0[2 * j],     hv.x, a);
                a = f2(w0[2 * j + 1], hv.y, a);
            }
            float sum = f2lo(a) + f2hi(a);
            sum += __shfl_xor_sync(0xFFFFFFFFu, sum, 1, 16);
            sum += __shfl_xor_sync(0xFFFFFFFFu, sum, 2, 16);
            sum += __shfl_xor_sync(0xFFFFFFFFu, sum, 4, 16);
            sum += __shfl_xor_sync(0xFFFFFFFFu, sum, 8, 16);
            if (s == (b & 15)) red[r * RP + b] = sum;
        }
        __syncthreads();

        // ======== epilogue L0: cell update, write h1[1-p] ========
        {
            float ig = sigm(red[(eu * 4 + 0) * RP + eb] + bias0[0]);
            float fg = sigm(red[(eu * 4 + 1) * RP + eb] + bias0[1]);
            float gv = tanh_fast(red[(eu * 4 + 2) * RP + eb] + bias0[2]);
            float og = sigm(red[(eu * 4 + 3) * RP + eb] + bias0[3]);
            c1 = fg * c1 + ig * gv;
            g_h1[1 - p][eb * HH + ej] = og * tanh_fast(c1);
        }

        gbar(++bi * NCTA);   // single grid barrier per step

        // ======== stage L1a: h1[1-p], skewed 32-data + 4-pad slices ========
        {
            const float4* hsrc = (const float4*)g_h1[1 - p];
            for (int idx = tid; idx < BB * 128; idx += NTHR) {
                int b = idx >> 7, q = idx & 127;
                *(float4*)(sm + b * HP + (q >> 3) * 36 + (q & 7) * 4) = hsrc[idx];
            }
        }
        __syncthreads();

        // ======== compute L1a: Wih1 . h1_new ========
#pragma unroll 2
        for (int b = 0; b < BB; ++b) {
            const ulonglong2* hp = (const ulonglong2*)(sm + b * HP + s * 36);
            ull a = 0ull;
#pragma unroll
            for (int j = 0; j < 8; ++j) {
                ulonglong2 hv = hp[j];
                a = f2(w1a[2 * j],     hv.x, a);
                a = f2(w1a[2 * j + 1], hv.y, a);
            }
            float sum = f2lo(a) + f2hi(a);
            sum += __shfl_xor_sync(0xFFFFFFFFu, sum, 1, 16);
            sum += __shfl_xor_sync(0xFFFFFFFFu, sum, 2, 16);
            sum += __shfl_xor_sync(0xFFFFFFFFu, sum, 4, 16);
            sum += __shfl_xor_sync(0xFFFFFFFFu, sum, 8, 16);
            if (s == (b & 15)) red[r * RP + b] = sum;
        }
        __syncthreads();

        // ======== stage L1b: h2[p], same skew ========
        {
            const float4* hsrc = (const float4*)g_h2[p];
            for (int idx = tid; idx < BB * 128; idx += NTHR) {
                int b = idx >> 7, q = idx & 127;
                *(float4*)(sm + b * HP + (q >> 3) * 36 + (q & 7) * 4) = hsrc[idx];
            }
        }
        __syncthreads();

        // ======== compute L1b: Whh1 . h2, accumulate into red ========
#pragma unroll 2
        for (int b = 0; b < BB; ++b) {
            const ulonglong2* hp = (const ulonglong2*)(sm + b * HP + s * 36);
            ull a = 0ull;
#pragma unroll
            for (int j = 0; j < 8; ++j) {
                ulonglong2 hv = hp[j];
                a = f2(w1b[2 * j],     hv.x, a);
                a = f2(w1b[2 * j + 1], hv.y, a);
            }
            float sum = f2lo(a) + f2hi(a);
            sum += __shfl_xor_sync(0xFFFFFFFFu, sum, 1, 16);
            sum += __shfl_xor_sync(0xFFFFFFFFu, sum, 2, 16);
            sum += __shfl_xor_sync(0xFFFFFFFFu, sum, 4, 16);
            sum += __shfl_xor_sync(0xFFFFFFFFu, sum, 8, 16);
            if (s == (b & 15)) red[r * RP + b] += sum;
        }
        __syncthreads();

        // ======== epilogue L1: cell update, write h2[1-p] ========
        {
            float ig = sigm(red[(eu * 4 + 0) * RP + eb] + bias1[0]);
            float fg = sigm(red[(eu * 4 + 1) * RP + eb] + bias1[1]);
            float gv = tanh_fast(red[(eu * 4 + 2) * RP + eb] + bias1[2]);
            float og = sigm(red[(eu * 4 + 3) * RP + eb] + bias1[3]);
            c2 = fg * c2 + ig * gv;
            g_h2[1 - p][eb * HH + ej] = og * tanh_fast(c2);
        }
        // loop-top __syncthreads orders red/sm reuse
    }

    gbar(++bi * NCTA);

    // FC head on last h2 (T even -> final state in buffer 0)
    if (cta == 0 && tid < BB) {
        const float* hf = g_h2[0];
        float a = fcb[0];
        for (int j = 0; j < HH; ++j) a = fmaf(hf[tid * HH + j], fcw[j], a);
        out[tid] = a;
    }
}

extern "C" void kernel_launch(void* const* d_in, const int* in_sizes, int n_in,
                              void* d_out, int out_size) {
    (void)in_sizes; (void)n_in; (void)out_size;
    const float* x    = (const float*)d_in[0];
    const float* Wih0 = (const float*)d_in[1];
    const float* Whh0 = (const float*)d_in[2];
    const float* bih0 = (const float*)d_in[3];
    const float* bhh0 = (const float*)d_in[4];
    const float* Wih1 = (const float*)d_in[5];
    const float* Whh1 = (const float*)d_in[6];
    const float* bih1 = (const float*)d_in[7];
    const float* bhh1 = (const float*)d_in[8];
    const float* fcw  = (const float*)d_in[9];
    const float* fcb  = (const float*)d_in[10];
    float* out = (float*)d_out;

    const int smem_bytes = (BB * HP + 16 * RP) * (int)sizeof(float);  // ~151.8 KB
    cudaFuncSetAttribute(lstm_kernel, cudaFuncAttributeMaxDynamicSharedMemorySize, smem_bytes);

    init_kernel<<<(BB * HH + NTHR - 1) / NTHR, NTHR>>>();
    lstm_kernel<<<NCTA, NTHR, smem_bytes>>>(x, Wih0, Whh0, bih0, bhh0,
                                            Wih1, Whh1, bih1, bhh1, fcw, fcb, out);
}

// round 6
// speedup vs baseline: 2.1440x; 2.1440x over previous
#include <cuda_runtime.h>
#include <cuda_bf16.h>
#include <stdint.h>

#define TT   512
#define HH   512
#define DIN  64
#define NCTA 64
#define NTHR 256
#define NKS0 108          // L0 ksteps: 3 * 576/16
#define NKS1 192          // L1 ksteps: 3 * 1024/16
#define NCH  6
#define CKS0 18
#define CKS1 32
#define BUFB 65536        // smem per B buffer (32 ks * 2KB)
#define SM_RED 131072
#define SM_TOTAL (131072 + 2*64*65*4)   // 164352 B

// ---- persistent device globals (no cudaMalloc allowed) ----
__device__ uint4    g_A0[32 * NKS0 * 128];          // 7.08 MB  A-fragment image L0
__device__ uint4    g_A1[32 * NKS1 * 128];          // 12.6 MB  A-fragment image L1
__device__ unsigned g_Bx[2][TT * 2048];             // x B-fragments [hi/lo][t]
__device__ unsigned g_Bh1[2][2][32 * 512];          // h1 B-image [hi/lo][parity]
__device__ unsigned g_Bh2[2][2][32 * 512];          // h2 B-image [hi/lo][parity]
__device__ float    g_h2f[64 * HH];
__device__ unsigned g_bar;

__device__ __forceinline__ float sigm(float x)      { return 1.f / (1.f + __expf(-x)); }
__device__ __forceinline__ float tanh_fast(float x) { return 2.f / (1.f + __expf(-2.f * x)) - 1.f; }

__device__ __forceinline__ uint32_t smem_u32(const void* p) {
    uint32_t a;
    asm("{ .reg .u64 t; cvta.to.shared.u64 t, %1; cvt.u32.u64 %0, t; }" : "=r"(a) : "l"(p));
    return a;
}
__device__ __forceinline__ void mma16816(float* d, const uint4 a, const uint2 b) {
    asm volatile(
        "mma.sync.aligned.m16n8k16.row.col.f32.bf16.bf16.f32 "
        "{%0,%1,%2,%3}, {%4,%5,%6,%7}, {%8,%9}, {%0,%1,%2,%3};"
        : "+f"(d[0]), "+f"(d[1]), "+f"(d[2]), "+f"(d[3])
        : "r"(a.x), "r"(a.y), "r"(a.z), "r"(a.w), "r"(b.x), "r"(b.y));
}
__device__ __forceinline__ unsigned pack_bf16(float a, float b) {
    return (unsigned)__bfloat16_as_ushort(__float2bfloat16(a)) |
           ((unsigned)__bfloat16_as_ushort(__float2bfloat16(b)) << 16);
}

__global__ void init_kernel() {
    int i = blockIdx.x * blockDim.x + threadIdx.x;
    if (i == 0) g_bar = 0u;
    if (i < 32 * 512) {
        g_Bh1[0][1][i] = 0u; g_Bh1[1][1][i] = 0u;
        g_Bh2[0][1][i] = 0u; g_Bh2[1][1][i] = 0u;
    }
}

// ---- prep: A weights into per-thread fragment order; x into B-fragment order ----
#define NA0U (32 * NKS0 * 128)
#define NAU  (32 * NKS0 * 128 + 32 * NKS1 * 128)
#define NXU  (2 * TT * 2048)

__global__ void prep_kernel(const float* __restrict__ x,
                            const float* __restrict__ Wih0, const float* __restrict__ Whh0,
                            const float* __restrict__ Wih1, const float* __restrict__ Whh1) {
    for (int i = blockIdx.x * blockDim.x + threadIdx.x; i < NAU;
         i += gridDim.x * blockDim.x) {
        const int isA1 = (i >= NA0U);
        const int i4 = isA1 ? i - NA0U : i;
        const int NKS = isA1 ? NKS1 : NKS0;
        const int lane = i4 & 31, mt = (i4 >> 5) & 3;
        const int rest = i4 >> 7;
        const int ks = rest % NKS, m = rest / NKS;
        const int gid = lane >> 2, tig = lane & 3;
        unsigned vals[4];
#pragma unroll
        for (int ri = 0; ri < 4; ++ri) {
            const int rl = mt * 16 + gid + ((ri & 1) * 8);
            const int kb = ks * 16 + tig * 2 + ((ri & 2) ? 8 : 0);
            const int rg = (rl & 3) * HH + m * 16 + (rl >> 2);
            float v0, v1; int islo;
            if (!isA1) {
                const int term = (kb >= 1152) ? 2 : ((kb >= 576) ? 1 : 0);
                const int k0 = kb - term * 576;
                v0 = (k0     < 512) ? Whh0[rg * HH + k0]     : Wih0[rg * DIN + k0 - 512];
                v1 = (k0 + 1 < 512) ? Whh0[rg * HH + k0 + 1] : Wih0[rg * DIN + k0 + 1 - 512];
                islo = (term == 2);
            } else {
                const int term = kb >> 10;
                const int k0 = kb & 1023;
                v0 = (k0 < 512) ? Wih1[rg * HH + k0] : Whh1[rg * HH + k0 - 512];
                v1 = (k0 < 512) ? Wih1[rg * HH + k0 + 1] : Whh1[rg * HH + k0 + 1 - 512];
                islo = (term == 2);
            }
            if (islo) {
                v0 -= __bfloat162float(__float2bfloat16(v0));
                v1 -= __bfloat162float(__float2bfloat16(v1));
            }
            vals[ri] = pack_bf16(v0, v1);
        }
        uint4 o; o.x = vals[0]; o.y = vals[1]; o.z = vals[2]; o.w = vals[3];
        if (!isA1) g_A0[i4] = o; else g_A1[i4] = o;
    }
    for (int j = blockIdx.x * blockDim.x + threadIdx.x; j < NXU;
         j += gridDim.x * blockDim.x) {
        const int im = (j >= TT * 2048);
        const int j2 = im ? j - TT * 2048 : j;
        const int t = j2 >> 11, e = j2 & 2047;
        const int reg = e & 1, lane = (e >> 1) & 31, ntl = (e >> 6) & 7, ksx = e >> 9;
        const int gid = lane >> 2, tig = lane & 3;
        const int nb = ntl * 8 + gid;
        const int kx = ksx * 16 + tig * 2 + reg * 8;
        float v0 = x[(nb * TT + t) * DIN + kx];
        float v1 = x[(nb * TT + t) * DIN + kx + 1];
        if (im) {
            v0 -= __bfloat162float(__float2bfloat16(v0));
            v1 -= __bfloat162float(__float2bfloat16(v1));
        }
        g_Bx[im][t * 2048 + e] = pack_bf16(v0, v1);
    }
}

__device__ __forceinline__ void gbar(unsigned target) {
    __syncthreads();
    if (threadIdx.x == 0) {
        __threadfence();
        atomicAdd(&g_bar, 1u);
        while (*((volatile unsigned*)&g_bar) < target) { }
        __threadfence();
    }
    __syncthreads();
}

__device__ __forceinline__ void stage_chunk(char* smem, int buf, int c, int layer,
                                            int pr, int p2, int t, int tid) {
    const int CKS = layer ? CKS1 : CKS0;
    const uint32_t sdst = smem_u32(smem) + buf * BUFB;
    for (int u = tid; u < CKS * 128; u += NTHR) {
        const int ksl = u >> 7, e16 = u & 127;
        const int ke = c * CKS + ksl;
        const uint4* src;
        if (!layer) {
            const int term = (ke >= 72) ? 2 : ((ke >= 36) ? 1 : 0);
            const int ws = ke - term * 36;
            const int im = (term == 1);
            if (ws < 32) src = (const uint4*)&g_Bh1[im][pr][ws * 512];
            else         src = (const uint4*)&g_Bx[im][t * 2048 + (ws - 32) * 512];
        } else {
            const int term = ke >> 6, ws = ke & 63;
            const int im = (term == 1);
            if (ws < 32) src = (const uint4*)&g_Bh1[im][pr][ws * 512];
            else         src = (const uint4*)&g_Bh2[im][p2][(ws - 32) * 512];
        }
        asm volatile("cp.async.cg.shared.global [%0], [%1], 16;"
                     :: "r"(sdst + u * 16), "l"(src + e16) : "memory");
    }
    asm volatile("cp.async.commit_group;" ::: "memory");
}

__global__ void __launch_bounds__(NTHR, 1) lstm_mma_kernel(
    const float* __restrict__ bih0, const float* __restrict__ bhh0,
    const float* __restrict__ bih1, const float* __restrict__ bhh1,
    const float* __restrict__ fcw,  const float* __restrict__ fcb,
    float* __restrict__ out)
{
    extern __shared__ char smem[];
    float* red = (float*)(smem + SM_RED);   // [kh 2][row 64][pitch 65]

    const int tid = threadIdx.x;
    const int lane = tid & 31, wid = tid >> 5;
    const int gid = lane >> 2, tig = lane & 3;
    const int cta = blockIdx.x;
    const int layer = (cta >= 32);
    const int m = cta & 31;
    const int mt2 = wid & 1, nh = (wid >> 1) & 1, kh = wid >> 2;
    const int CKS = layer ? CKS1 : CKS0, HKS = CKS >> 1;
    const uint4* Ab = layer ? (g_A1 + (size_t)m * NKS1 * 128)
                            : (g_A0 + (size_t)m * NKS0 * 128);

    const int n = tid & 63, vpA = tid >> 6;
    const float* bi_ = layer ? bih1 : bih0;
    const float* bh_ = layer ? bhh1 : bhh0;
    float bias[4][4], cst[4] = {0.f, 0.f, 0.f, 0.f};
#pragma unroll
    for (int vi = 0; vi < 2; ++vi)
#pragma unroll
        for (int w = 0; w < 2; ++w) {
            const int j = 2 * (vpA + vi * 4) + w, si = vi * 2 + w;
            const int jj = m * 16 + j;
#pragma unroll
            for (int g = 0; g < 4; ++g)
                bias[si][g] = bi_[g * HH + jj] + bh_[g * HH + jj];
        }

    unsigned bctr = 0;
    for (int i = 0; i <= TT; ++i) {
        const int act = layer ? (i >= 1) : (i < TT);
        if (act) {
            const int pr = (i + 1) & 1;   // h1(prev) parity
            const int p2 = i & 1;         // h2(prev) parity (L1 read / L0 write)
            const int t = i;
            float d[2][4][4];
#pragma unroll
            for (int a = 0; a < 2; ++a)
#pragma unroll
                for (int b = 0; b < 4; ++b)
#pragma unroll
                    for (int c2 = 0; c2 < 4; ++c2) d[a][b][c2] = 0.f;

            stage_chunk(smem, 0, 0, layer, pr, p2, t, tid);
            for (int c = 0; c < NCH; ++c) {
                if (c + 1 < NCH) {
                    stage_chunk(smem, (c + 1) & 1, c + 1, layer, pr, p2, t, tid);
                    asm volatile("cp.async.wait_group 1;" ::: "memory");
                } else {
                    asm volatile("cp.async.wait_group 0;" ::: "memory");
                }
                __syncthreads();
                const uint32_t* bs = (const uint32_t*)(smem + (c & 1) * BUFB);
                const int ksbase = c * CKS + kh * HKS;
#pragma unroll 2
                for (int ksl = 0; ksl < HKS; ++ksl) {
                    const int ks = ksbase + ksl;
                    const uint4 a0 = Ab[ks * 128 + (mt2 * 2) * 32 + lane];
                    const uint4 a1 = Ab[ks * 128 + (mt2 * 2 + 1) * 32 + lane];
                    const int ksb = kh * HKS + ksl;
#pragma unroll
                    for (int nt = 0; nt < 4; ++nt) {
                        const uint2 bv = *(const uint2*)(bs + ((ksb * 8 + nh * 4 + nt) * 32 + lane) * 2);
                        mma16816(d[0][nt], a0, bv);
                        mma16816(d[1][nt], a1, bv);
                    }
                }
                __syncthreads();
            }

            // D fragments -> red (K-split kept separate, summed at read)
#pragma unroll
            for (int h = 0; h < 2; ++h) {
                const int row = (mt2 * 2 + h) * 16 + gid;
#pragma unroll
                for (int nt = 0; nt < 4; ++nt) {
                    const int col = nh * 32 + nt * 8 + tig * 2;
                    red[(kh * 64 + row) * 65 + col]       = d[h][nt][0];
                    red[(kh * 64 + row) * 65 + col + 1]   = d[h][nt][1];
                    red[(kh * 64 + row + 8) * 65 + col]   = d[h][nt][2];
                    red[(kh * 64 + row + 8) * 65 + col + 1] = d[h][nt][3];
                }
            }
            __syncthreads();

            // cell update + h write in B-fragment order
            const int wp = layer ? pr : p2;
            unsigned* imh = layer ? g_Bh2[0][wp] : g_Bh1[0][wp];
            unsigned* iml = layer ? g_Bh2[1][wp] : g_Bh1[1][wp];
#pragma unroll
            for (int vi = 0; vi < 2; ++vi) {
                const int vp = vpA + vi * 4;
                float hv[2];
#pragma unroll
                for (int w = 0; w < 2; ++w) {
                    const int j = 2 * vp + w, si = vi * 2 + w;
                    const float s0 = red[(j * 4 + 0) * 65 + n] + red[(j * 4 + 0 + 64) * 65 + n] + bias[si][0];
                    const float s1 = red[(j * 4 + 1) * 65 + n] + red[(j * 4 + 1 + 64) * 65 + n] + bias[si][1];
                    const float s2 = red[(j * 4 + 2) * 65 + n] + red[(j * 4 + 2 + 64) * 65 + n] + bias[si][2];
                    const float s3 = red[(j * 4 + 3) * 65 + n] + red[(j * 4 + 3 + 64) * 65 + n] + bias[si][3];
                    const float ig = sigm(s0), fg = sigm(s1);
                    const float gv = tanh_fast(s2), og = sigm(s3);
                    cst[si] = fg * cst[si] + ig * gv;
                    hv[w] = og * tanh_fast(cst[si]);
                    if (layer && i == TT) g_h2f[n * HH + m * 16 + j] = hv[w];
                }
                const unsigned ph = pack_bf16(hv[0], hv[1]);
                const float l0 = hv[0] - __bfloat162float(__float2bfloat16(hv[0]));
                const float l1 = hv[1] - __bfloat162float(__float2bfloat16(hv[1]));
                const unsigned pl = pack_bf16(l0, l1);
                const int idx = m * 512 + (((n >> 3) * 32 + (n & 7) * 4 + (vp & 3)) * 2) + (vp >> 2);
                imh[idx] = ph;
                iml[idx] = pl;
            }
        }
        gbar(++bctr * NCTA);
    }

    // FC head on last h2
    if (cta == 0) {
        const int b = tid >> 2, jq = tid & 3;
        float a = 0.f;
        for (int j = jq * 128; j < jq * 128 + 128; ++j)
            a = fmaf(g_h2f[b * HH + j], fcw[j], a);
        a += __shfl_xor_sync(0xFFFFFFFFu, a, 1);
        a += __shfl_xor_sync(0xFFFFFFFFu, a, 2);
        if (jq == 0) out[b] = a + fcb[0];
    }
}

extern "C" void kernel_launch(void* const* d_in, const int* in_sizes, int n_in,
                              void* d_out, int out_size) {
    (void)in_sizes; (void)n_in; (void)out_size;
    const float* x    = (const float*)d_in[0];
    const float* Wih0 = (const float*)d_in[1];
    const float* Whh0 = (const float*)d_in[2];
    const float* bih0 = (const float*)d_in[3];
    const float* bhh0 = (const float*)d_in[4];
    const float* Wih1 = (const float*)d_in[5];
    const float* Whh1 = (const float*)d_in[6];
    const float* bih1 = (const float*)d_in[7];
    const float* bhh1 = (const float*)d_in[8];
    const float* fcw  = (const float*)d_in[9];
    const float* fcb  = (const float*)d_in[10];
    float* out = (float*)d_out;

    cudaFuncSetAttribute(lstm_mma_kernel, cudaFuncAttributeMaxDynamicSharedMemorySize, SM_TOTAL);

    init_kernel<<<64, 256>>>();
    prep_kernel<<<512, 256>>>(x, Wih0, Whh0, Wih1, Whh1);
    lstm_mma_kernel<<<NCTA, NTHR, SM_TOTAL>>>(bih0, bhh0, bih1, bhh1, fcw, fcb, out);
}

// round 7
// speedup vs baseline: 2.4794x; 1.1564x over previous
#include <cuda_runtime.h>
#include <cuda_bf16.h>
#include <stdint.h>

#define TT   512
#define HH   512
#define DIN  64
#define NCTA 128
#define NTHR 256
#define NKS0 108          // L0 ksteps: 3 * 576/16
#define NKS1 192          // L1 ksteps: 3 * 1024/16
#define NCH0 9
#define NCH1 8
#define CKS0 12
#define CKS1 24
#define BUFB 24576        // smem per B buffer (24 ks * 1KB half-N)
#define SM_RED (2*BUFB)
#define SM_TOTAL (SM_RED + 4*64*33*4)   // 82944 B

// ---- persistent device globals (no cudaMalloc allowed) ----
__device__ uint4    g_A0[32 * NKS0 * 128];          // 7.08 MB  A-fragment image L0
__device__ uint4    g_A1[32 * NKS1 * 128];          // 12.6 MB  A-fragment image L1
__device__ unsigned g_Bx[2][TT * 2048];             // x B-fragments [hi/lo][t]
__device__ unsigned g_Bh1[2][2][32 * 512];          // h1 B-image [hi/lo][parity]
__device__ unsigned g_Bh2[2][2][32 * 512];          // h2 B-image [hi/lo][parity]
__device__ float    g_h2f[64 * HH];
__device__ unsigned g_bar;

__device__ __forceinline__ float sigm(float x)      { return 1.f / (1.f + __expf(-x)); }
__device__ __forceinline__ float tanh_fast(float x) { return 2.f / (1.f + __expf(-2.f * x)) - 1.f; }

__device__ __forceinline__ uint32_t smem_u32(const void* p) {
    uint32_t a;
    asm("{ .reg .u64 t; cvta.to.shared.u64 t, %1; cvt.u32.u64 %0, t; }" : "=r"(a) : "l"(p));
    return a;
}
__device__ __forceinline__ void mma16816(float* d, const uint4 a, const uint2 b) {
    asm volatile(
        "mma.sync.aligned.m16n8k16.row.col.f32.bf16.bf16.f32 "
        "{%0,%1,%2,%3}, {%4,%5,%6,%7}, {%8,%9}, {%0,%1,%2,%3};"
        : "+f"(d[0]), "+f"(d[1]), "+f"(d[2]), "+f"(d[3])
        : "r"(a.x), "r"(a.y), "r"(a.z), "r"(a.w), "r"(b.x), "r"(b.y));
}
__device__ __forceinline__ unsigned pack_bf16(float a, float b) {
    return (unsigned)__bfloat16_as_ushort(__float2bfloat16(a)) |
           ((unsigned)__bfloat16_as_ushort(__float2bfloat16(b)) << 16);
}

__global__ void init_kernel() {
    int i = blockIdx.x * blockDim.x + threadIdx.x;
    if (i == 0) g_bar = 0u;
    if (i < 32 * 512) {
        g_Bh1[0][1][i] = 0u; g_Bh1[1][1][i] = 0u;
        g_Bh2[0][1][i] = 0u; g_Bh2[1][1][i] = 0u;
    }
}

// ---- prep: A weights into per-thread fragment order; x into B-fragment order ----
#define NA0U (32 * NKS0 * 128)
#define NAU  (32 * NKS0 * 128 + 32 * NKS1 * 128)
#define NXU  (2 * TT * 2048)

__global__ void prep_kernel(const float* __restrict__ x,
                            const float* __restrict__ Wih0, const float* __restrict__ Whh0,
                            const float* __restrict__ Wih1, const float* __restrict__ Whh1) {
    for (int i = blockIdx.x * blockDim.x + threadIdx.x; i < NAU;
         i += gridDim.x * blockDim.x) {
        const int isA1 = (i >= NA0U);
        const int i4 = isA1 ? i - NA0U : i;
        const int NKS = isA1 ? NKS1 : NKS0;
        const int lane = i4 & 31, mt = (i4 >> 5) & 3;
        const int rest = i4 >> 7;
        const int ks = rest % NKS, m = rest / NKS;
        const int gid = lane >> 2, tig = lane & 3;
        unsigned vals[4];
#pragma unroll
        for (int ri = 0; ri < 4; ++ri) {
            const int rl = mt * 16 + gid + ((ri & 1) * 8);
            const int kb = ks * 16 + tig * 2 + ((ri & 2) ? 8 : 0);
            const int rg = (rl & 3) * HH + m * 16 + (rl >> 2);
            float v0, v1; int islo;
            if (!isA1) {
                const int term = (kb >= 1152) ? 2 : ((kb >= 576) ? 1 : 0);
                const int k0 = kb - term * 576;
                v0 = (k0     < 512) ? Whh0[rg * HH + k0]     : Wih0[rg * DIN + k0 - 512];
                v1 = (k0 + 1 < 512) ? Whh0[rg * HH + k0 + 1] : Wih0[rg * DIN + k0 + 1 - 512];
                islo = (term == 2);
            } else {
                const int term = kb >> 10;
                const int k0 = kb & 1023;
                v0 = (k0 < 512) ? Wih1[rg * HH + k0] : Whh1[rg * HH + k0 - 512];
                v1 = (k0 < 512) ? Wih1[rg * HH + k0 + 1] : Whh1[rg * HH + k0 + 1 - 512];
                islo = (term == 2);
            }
            if (islo) {
                v0 -= __bfloat162float(__float2bfloat16(v0));
                v1 -= __bfloat162float(__float2bfloat16(v1));
            }
            vals[ri] = pack_bf16(v0, v1);
        }
        uint4 o; o.x = vals[0]; o.y = vals[1]; o.z = vals[2]; o.w = vals[3];
        if (!isA1) g_A0[i4] = o; else g_A1[i4] = o;
    }
    for (int j = blockIdx.x * blockDim.x + threadIdx.x; j < NXU;
         j += gridDim.x * blockDim.x) {
        const int im = (j >= TT * 2048);
        const int j2 = im ? j - TT * 2048 : j;
        const int t = j2 >> 11, e = j2 & 2047;
        const int reg = e & 1, lane = (e >> 1) & 31, ntl = (e >> 6) & 7, ksx = e >> 9;
        const int gid = lane >> 2, tig = lane & 3;
        const int nb = ntl * 8 + gid;
        const int kx = ksx * 16 + tig * 2 + reg * 8;
        float v0 = x[(nb * TT + t) * DIN + kx];
        float v1 = x[(nb * TT + t) * DIN + kx + 1];
        if (im) {
            v0 -= __bfloat162float(__float2bfloat16(v0));
            v1 -= __bfloat162float(__float2bfloat16(v1));
        }
        g_Bx[im][t * 2048 + e] = pack_bf16(v0, v1);
    }
}

__device__ __forceinline__ void gbar(unsigned target) {
    __syncthreads();
    if (threadIdx.x == 0) {
        __threadfence();
        atomicAdd(&g_bar, 1u);
        while (*((volatile unsigned*)&g_bar) < target) { }
        __threadfence();
    }
    __syncthreads();
}

// Stage this CTA's batch-half of chunk c into buffer buf (1KB per kstep).
__device__ __forceinline__ void stage_chunk(char* smem, int buf, int c, int layer,
                                            int pr, int p2, int t, int nh2, int tid) {
    const int CKS = layer ? CKS1 : CKS0;
    const uint32_t sdst = smem_u32(smem) + buf * BUFB;
    for (int u = tid; u < CKS * 64; u += NTHR) {
        const int ksl = u >> 6, e = u & 63;
        const int ke = c * CKS + ksl;
        const uint4* src;
        if (!layer) {
            const int term = (ke >= 72) ? 2 : ((ke >= 36) ? 1 : 0);
            const int ws = ke - term * 36;
            const int im = (term == 1);
            if (ws < 32) src = (const uint4*)&g_Bh1[im][pr][ws * 512];
            else         src = (const uint4*)&g_Bx[im][t * 2048 + (ws - 32) * 512];
        } else {
            const int term = ke >> 6, ws = ke & 63;
            const int im = (term == 1);
            if (ws < 32) src = (const uint4*)&g_Bh1[im][pr][ws * 512];
            else         src = (const uint4*)&g_Bh2[im][p2][(ws - 32) * 512];
        }
        asm volatile("cp.async.cg.shared.global [%0], [%1], 16;"
                     :: "r"(sdst + u * 16), "l"(src + nh2 * 64 + e) : "memory");
    }
    asm volatile("cp.async.commit_group;" ::: "memory");
}

// One chunk of MMAs for this warp: QKS ksteps, A front-batched into registers.
template<int QKS>
__device__ __forceinline__ void do_chunk(float d[2][4][4], const uint4* __restrict__ Ab,
                                         const uint32_t* bs, int c, int kh, int mt2, int lane) {
    const int CKS = QKS * 4;
    const int ks0 = c * CKS + kh * QKS;
    const int ksb0 = kh * QKS;
    uint4 a0[QKS], a1[QKS];
#pragma unroll
    for (int ksl = 0; ksl < QKS; ++ksl) {
        a0[ksl] = Ab[(ks0 + ksl) * 128 + (mt2 * 2) * 32 + lane];
        a1[ksl] = Ab[(ks0 + ksl) * 128 + (mt2 * 2 + 1) * 32 + lane];
    }
#pragma unroll
    for (int ksl = 0; ksl < QKS; ++ksl) {
#pragma unroll
        for (int nt = 0; nt < 4; ++nt) {
            const uint2 bv = *(const uint2*)(bs + ((ksb0 + ksl) * 256 + nt * 64 + lane * 2));
            mma16816(d[0][nt], a0[ksl], bv);
            mma16816(d[1][nt], a1[ksl], bv);
        }
    }
}

__global__ void __launch_bounds__(NTHR, 1) lstm_mma_kernel(
    const float* __restrict__ bih0, const float* __restrict__ bhh0,
    const float* __restrict__ bih1, const float* __restrict__ bhh1,
    const float* __restrict__ fcw,  const float* __restrict__ fcb,
    float* __restrict__ out)
{
    extern __shared__ char smem[];
    float* red = (float*)(smem + SM_RED);   // [kh 4][row 64][pitch 33]

    const int tid = threadIdx.x;
    const int lane = tid & 31, wid = tid >> 5;
    const int gid = lane >> 2, tig = lane & 3;
    const int cta = blockIdx.x;
    const int layer = cta >> 6;
    const int nh2 = (cta >> 5) & 1;
    const int m = cta & 31;
    const int mt2 = wid & 1, kh = wid >> 1;        // warps = mt2(2) x kh(4)
    const uint4* Ab = layer ? (g_A1 + (size_t)m * NKS1 * 128)
                            : (g_A0 + (size_t)m * NKS0 * 128);
    const int NCH = layer ? NCH1 : NCH0;

    // epilogue mapping: thread -> 1 batch (this half) x 2 units
    const int np = tid & 31;                // batch-local 0..31
    const int n = nh2 * 32 + np;            // global batch
    const int vp = tid >> 5;                // 0..7 -> units 2vp, 2vp+1
    const float* bi_ = layer ? bih1 : bih0;
    const float* bh_ = layer ? bhh1 : bhh0;
    float bias[2][4], cst[2] = {0.f, 0.f};
#pragma unroll
    for (int w = 0; w < 2; ++w) {
        const int jj = m * 16 + 2 * vp + w;
#pragma unroll
        for (int g = 0; g < 4; ++g) bias[w][g] = bi_[g * HH + jj] + bh_[g * HH + jj];
    }

    unsigned bctr = 0;
    for (int i = 0; i <= TT; ++i) {
        const int act = layer ? (i >= 1) : (i < TT);
        if (act) {
            const int pr = (i + 1) & 1;   // h1(prev) parity
            const int p2 = i & 1;         // h2(prev) parity / L0 write parity
            const int t = i;
            float d[2][4][4];
#pragma unroll
            for (int a = 0; a < 2; ++a)
#pragma unroll
                for (int b = 0; b < 4; ++b)
#pragma unroll
                    for (int c2 = 0; c2 < 4; ++c2) d[a][b][c2] = 0.f;

            stage_chunk(smem, 0, 0, layer, pr, p2, t, nh2, tid);
            for (int c = 0; c < NCH; ++c) {
                if (c + 1 < NCH) {
                    stage_chunk(smem, (c + 1) & 1, c + 1, layer, pr, p2, t, nh2, tid);
                    asm volatile("cp.async.wait_group 1;" ::: "memory");
                } else {
                    asm volatile("cp.async.wait_group 0;" ::: "memory");
                }
                __syncthreads();
                const uint32_t* bs = (const uint32_t*)(smem + (c & 1) * BUFB);
                if (!layer) do_chunk<3>(d, Ab, bs, c, kh, mt2, lane);
                else        do_chunk<6>(d, Ab, bs, c, kh, mt2, lane);
                __syncthreads();
            }

            // D fragments -> red[kh][row][np]
#pragma unroll
            for (int h = 0; h < 2; ++h) {
                const int row = (mt2 * 2 + h) * 16 + gid;
#pragma unroll
                for (int nt = 0; nt < 4; ++nt) {
                    const int col = nt * 8 + tig * 2;
                    red[(kh * 64 + row) * 33 + col]         = d[h][nt][0];
                    red[(kh * 64 + row) * 33 + col + 1]     = d[h][nt][1];
                    red[(kh * 64 + row + 8) * 33 + col]     = d[h][nt][2];
                    red[(kh * 64 + row + 8) * 33 + col + 1] = d[h][nt][3];
                }
            }
            __syncthreads();

            // cell update (sum 4 K-partials) + h write in B-fragment order
            const int wp = layer ? pr : p2;
            unsigned* imh = layer ? g_Bh2[0][wp] : g_Bh1[0][wp];
            unsigned* iml = layer ? g_Bh2[1][wp] : g_Bh1[1][wp];
            float hv[2];
#pragma unroll
            for (int w = 0; w < 2; ++w) {
                const int j = 2 * vp + w;
                float s[4];
#pragma unroll
                for (int g = 0; g < 4; ++g) {
                    float acc = bias[w][g];
#pragma unroll
                    for (int k4 = 0; k4 < 4; ++k4)
                        acc += red[(k4 * 64 + j * 4 + g) * 33 + np];
                    s[g] = acc;
                }
                const float ig = sigm(s[0]), fg = sigm(s[1]);
                const float gv = tanh_fast(s[2]), og = sigm(s[3]);
                cst[w] = fg * cst[w] + ig * gv;
                hv[w] = og * tanh_fast(cst[w]);
                if (layer && i == TT) g_h2f[n * HH + m * 16 + j] = hv[w];
            }
            const unsigned ph = pack_bf16(hv[0], hv[1]);
            const float l0 = hv[0] - __bfloat162float(__float2bfloat16(hv[0]));
            const float l1 = hv[1] - __bfloat162float(__float2bfloat16(hv[1]));
            const unsigned pl = pack_bf16(l0, l1);
            const int idx = m * 512 + (n >> 3) * 64 + (n & 7) * 8 + (vp & 3) * 2 + (vp >> 2);
            imh[idx] = ph;
            iml[idx] = pl;
        }
        gbar(++bctr * NCTA);
    }

    // FC head on last h2
    if (cta == 0) {
        const int b = tid >> 2, jq = tid & 3;
        float a = 0.f;
        for (int j = jq * 128; j < jq * 128 + 128; ++j)
            a = fmaf(g_h2f[b * HH + j], fcw[j], a);
        a += __shfl_xor_sync(0xFFFFFFFFu, a, 1);
        a += __shfl_xor_sync(0xFFFFFFFFu, a, 2);
        if (jq == 0) out[b] = a + fcb[0];
    }
}

extern "C" void kernel_launch(void* const* d_in, const int* in_sizes, int n_in,
                              void* d_out, int out_size) {
    (void)in_sizes; (void)n_in; (void)out_size;
    const float* x    = (const float*)d_in[0];
    const float* Wih0 = (const float*)d_in[1];
    const float* Whh0 = (const float*)d_in[2];
    const float* bih0 = (const float*)d_in[3];
    const float* bhh0 = (const float*)d_in[4];
    const float* Wih1 = (const float*)d_in[5];
    const float* Whh1 = (const float*)d_in[6];
    const float* bih1 = (const float*)d_in[7];
    const float* bhh1 = (const float*)d_in[8];
    const float* fcw  = (const float*)d_in[9];
    const float* fcb  = (const float*)d_in[10];
    float* out = (float*)d_out;

    cudaFuncSetAttribute(lstm_mma_kernel, cudaFuncAttributeMaxDynamicSharedMemorySize, SM_TOTAL);

    init_kernel<<<64, 256>>>();
    prep_kernel<<<512, 256>>>(x, Wih0, Whh0, Wih1, Whh1);
    lstm_mma_kernel<<<NCTA, NTHR, SM_TOTAL>>>(bih0, bhh0, bih1, bhh1, fcw, fcb, out);
}

// round 8
// speedup vs baseline: 2.6528x; 1.0700x over previous
#include <cuda_runtime.h>
#include <cuda_bf16.h>
#include <stdint.h>

#define TT   512
#define HH   512
#define DIN  64
#define NCTA 128
#define NTHR 256
#define NKS0 108          // L0 ksteps: 3 * 576/16
#define NKS1 192          // L1 ksteps: 3 * 1024/16
#define CKS  12           // ksteps per chunk
#define NCHT 25           // 16 L1 chunks + 9 L0 chunks
#define RING 8
#define LOOK 6
#define CBYTES 12288      // 12 ks * 32 batch * 16 k * 2B
#define SM_RED (RING * CBYTES)              // 98304
#define SM_TOTAL (SM_RED + 4*32*33*4)       // 115200

// ---- persistent device globals (no cudaMalloc allowed) ----
__device__ uint4    g_A0[64 * NKS0 * 64];           // 7.08 MB  L0 A-fragments (M32 tiles)
__device__ uint4    g_A1[64 * NKS1 * 64];           // 12.6 MB  L1 A-fragments
__device__ unsigned g_Bx[2][TT * 2048];             // x B-fragments [hi/lo][t]
__device__ unsigned g_Bh1[2][2][32 * 512];          // h1 B-image [hi/lo][parity]
__device__ unsigned g_Bh2[2][2][32 * 512];          // h2 B-image [hi/lo][parity]
__device__ float    g_h2f[64 * HH];
__device__ unsigned g_bar;

__device__ __forceinline__ float sigm(float x)      { return 1.f / (1.f + __expf(-x)); }
__device__ __forceinline__ float tanh_fast(float x) { return 2.f / (1.f + __expf(-2.f * x)) - 1.f; }

__device__ __forceinline__ uint32_t smem_u32(const void* p) {
    uint32_t a;
    asm("{ .reg .u64 t; cvta.to.shared.u64 t, %1; cvt.u32.u64 %0, t; }" : "=r"(a) : "l"(p));
    return a;
}
__device__ __forceinline__ void mma16816(float* d, const uint4 a, const uint2 b) {
    asm volatile(
        "mma.sync.aligned.m16n8k16.row.col.f32.bf16.bf16.f32 "
        "{%0,%1,%2,%3}, {%4,%5,%6,%7}, {%8,%9}, {%0,%1,%2,%3};"
        : "+f"(d[0]), "+f"(d[1]), "+f"(d[2]), "+f"(d[3])
        : "r"(a.x), "r"(a.y), "r"(a.z), "r"(a.w), "r"(b.x), "r"(b.y));
}
__device__ __forceinline__ unsigned pack_bf16(float a, float b) {
    return (unsigned)__bfloat16_as_ushort(__float2bfloat16(a)) |
           ((unsigned)__bfloat16_as_ushort(__float2bfloat16(b)) << 16);
}

// ---- prep: init state + A weights into fragment order + x into B-fragment order ----
#define NA0U (64 * NKS0 * 64)
#define NAU  (64 * NKS0 * 64 + 64 * NKS1 * 64)
#define NXU  (2 * TT * 2048)

__global__ void prep_kernel(const float* __restrict__ x,
                            const float* __restrict__ Wih0, const float* __restrict__ Whh0,
                            const float* __restrict__ Wih1, const float* __restrict__ Whh1) {
    const int gtid = blockIdx.x * blockDim.x + threadIdx.x;
    if (gtid == 0) g_bar = 0u;
    for (int i = gtid; i < 32 * 512; i += gridDim.x * blockDim.x) {
        g_Bh1[0][1][i] = 0u; g_Bh1[1][1][i] = 0u;
        g_Bh2[0][1][i] = 0u; g_Bh2[1][1][i] = 0u;
    }
    for (int i = gtid; i < NAU; i += gridDim.x * blockDim.x) {
        const int isA1 = (i >= NA0U);
        const int i4 = isA1 ? i - NA0U : i;
        const int NKS = isA1 ? NKS1 : NKS0;
        const int lane = i4 & 31, mt = (i4 >> 5) & 1;
        const int rest = i4 >> 6;
        const int ks = rest % NKS, m = rest / NKS;      // m: 0..63 (M32 tile)
        const int gid = lane >> 2, tig = lane & 3;
        unsigned vals[4];
#pragma unroll
        for (int ri = 0; ri < 4; ++ri) {
            const int rl = mt * 16 + gid + ((ri & 1) * 8);      // 0..31
            const int kb = ks * 16 + tig * 2 + ((ri & 2) ? 8 : 0);
            const int rg = (rl & 3) * HH + m * 8 + (rl >> 2);
            float v0, v1; int islo;
            if (!isA1) {
                const int term = (kb >= 1152) ? 2 : ((kb >= 576) ? 1 : 0);
                const int k0 = kb - term * 576;
                v0 = (k0     < 512) ? Whh0[rg * HH + k0]     : Wih0[rg * DIN + k0 - 512];
                v1 = (k0 + 1 < 512) ? Whh0[rg * HH + k0 + 1] : Wih0[rg * DIN + k0 + 1 - 512];
                islo = (term == 2);
            } else {
                const int term = kb >> 10;
                const int k0 = kb & 1023;
                v0 = (k0 < 512) ? Wih1[rg * HH + k0] : Whh1[rg * HH + k0 - 512];
                v1 = (k0 < 512) ? Wih1[rg * HH + k0 + 1] : Whh1[rg * HH + k0 + 1 - 512];
                islo = (term == 2);
            }
            if (islo) {
                v0 -= __bfloat162float(__float2bfloat16(v0));
                v1 -= __bfloat162float(__float2bfloat16(v1));
            }
            vals[ri] = pack_bf16(v0, v1);
        }
        uint4 o; o.x = vals[0]; o.y = vals[1]; o.z = vals[2]; o.w = vals[3];
        if (!isA1) g_A0[i4] = o; else g_A1[i4] = o;
    }
    for (int j = gtid; j < NXU; j += gridDim.x * blockDim.x) {
        const int im = (j >= TT * 2048);
        const int j2 = im ? j - TT * 2048 : j;
        const int t = j2 >> 11, e = j2 & 2047;
        const int reg = e & 1, lane = (e >> 1) & 31, ntl = (e >> 6) & 7, ksx = e >> 9;
        const int gid = lane >> 2, tig = lane & 3;
        const int nb = ntl * 8 + gid;
        const int kx = ksx * 16 + tig * 2 + reg * 8;
        float v0 = x[(nb * TT + t) * DIN + kx];
        float v1 = x[(nb * TT + t) * DIN + kx + 1];
        if (im) {
            v0 -= __bfloat162float(__float2bfloat16(v0));
            v1 -= __bfloat162float(__float2bfloat16(v1));
        }
        g_Bx[im][t * 2048 + e] = pack_bf16(v0, v1);
    }
}

__device__ __forceinline__ void gbar(unsigned target) {
    __syncthreads();
    if (threadIdx.x == 0) {
        __threadfence();
        atomicAdd(&g_bar, 1u);
        while (*((volatile unsigned*)&g_bar) < target) { }
        __threadfence();
    }
    __syncthreads();
}

// Stage chunk cc (absolute id 0..24; <16 = L1, >=16 = L0) into ring buffer cc&7.
// Always commits a group (empty when cc out of range) so wait_group counts stay constant.
__device__ __forceinline__ void stage_or_empty(uint32_t sbase, int cc, int chi,
                                               int pr, int p2, int t, int nh2, int tid) {
    if (cc < chi) {
        const uint32_t sdst = sbase + (cc & 7) * CBYTES;
        for (int u = tid; u < CKS * 64; u += NTHR) {
            const int ksl = u >> 6, e = u & 63;
            const uint4* src;
            if (cc < 16) {
                const int ke = cc * CKS + ksl;
                const int term = ke >> 6, ws = ke & 63;
                const int im = (term == 1);
                if (ws < 32) src = (const uint4*)&g_Bh1[im][pr][ws * 512];
                else         src = (const uint4*)&g_Bh2[im][p2][(ws - 32) * 512];
            } else {
                const int ke = (cc - 16) * CKS + ksl;
                const int term = (ke >= 72) ? 2 : ((ke >= 36) ? 1 : 0);
                const int ws = ke - term * 36;
                const int im = (term == 1);
                if (ws < 32) src = (const uint4*)&g_Bh1[im][pr][ws * 512];
                else         src = (const uint4*)&g_Bx[im][t * 2048 + (ws - 32) * 512];
            }
            asm volatile("cp.async.cg.shared.global [%0], [%1], 16;"
                         :: "r"(sdst + u * 16), "l"(src + nh2 * 64 + e) : "memory");
        }
    }
    asm volatile("cp.async.commit_group;" ::: "memory");
}

__global__ void __launch_bounds__(NTHR, 1) lstm_mma_kernel(
    const float* __restrict__ bih0, const float* __restrict__ bhh0,
    const float* __restrict__ bih1, const float* __restrict__ bhh1,
    const float* __restrict__ fcw,  const float* __restrict__ fcb,
    float* __restrict__ out)
{
    extern __shared__ char smem[];
    const uint32_t sbase = smem_u32(smem);
    float* red = (float*)(smem + SM_RED);   // [kh 4][row 32][pitch 33]

    const int tid = threadIdx.x;
    const int lane = tid & 31, wid = tid >> 5;
    const int gid = lane >> 2, tig = lane & 3;
    const int cta = blockIdx.x;
    const int nh2 = cta >> 6;               // batch half
    const int m = cta & 63;                 // M32 tile (same index both layers)
    const int mt2 = wid & 1, kh = wid >> 1; // warps = mt2(2) x kh(4)
    const uint4* Ab1 = g_A1 + (size_t)m * NKS1 * 64;
    const uint4* Ab0 = g_A0 + (size_t)m * NKS0 * 64;

    // epilogue mapping (threads 0..127): vp = unit pair (0..3), np = batch-local
    const int np = tid & 31, vp = tid >> 5;
    const int n = nh2 * 32 + np;
    float bias0[2][4], bias1[2][4], c1s[2] = {0.f, 0.f}, c2s[2] = {0.f, 0.f};
    if (tid < 128) {
#pragma unroll
        for (int w = 0; w < 2; ++w) {
            const int jj = m * 8 + 2 * vp + w;
#pragma unroll
            for (int g = 0; g < 4; ++g) {
                bias0[w][g] = bih0[g * HH + jj] + bhh0[g * HH + jj];
                bias1[w][g] = bih1[g * HH + jj] + bhh1[g * HH + jj];
            }
        }
    }

    float d[4][4];
#pragma unroll
    for (int a = 0; a < 4; ++a)
#pragma unroll
        for (int b = 0; b < 4; ++b) d[a][b] = 0.f;

    unsigned bctr = 0;
    for (int i = 0; i <= TT; ++i) {
        const int pr = (i + 1) & 1;          // h1(i-1) parity
        const int p2 = i & 1;                // h2(i-2) parity / h1(i) write parity
        const int t = i;
        const int clo = (i == 0) ? 16 : 0;
        const int chi = (i == TT) ? 16 : NCHT;

        // prime the ring
#pragma unroll
        for (int j = 0; j < LOOK; ++j)
            stage_or_empty(sbase, clo + j, chi, pr, p2, t, nh2, tid);

        for (int c = clo; c < chi; ++c) {
            stage_or_empty(sbase, c + LOOK, chi, pr, p2, t, nh2, tid);
            asm volatile("cp.async.wait_group %0;" :: "n"(LOOK) : "memory");
            __syncthreads();

            // MMA on chunk c
            {
                const uint4* Ab = (c < 16) ? Ab1 : Ab0;
                const int ks0 = (c < 16) ? c * CKS : (c - 16) * CKS;
                const uint32_t* bs = (const uint32_t*)(smem + (c & 7) * CBYTES);
                const int kb0 = kh * 3;
                uint4 a[3];
#pragma unroll
                for (int ksl = 0; ksl < 3; ++ksl)
                    a[ksl] = Ab[(ks0 + kb0 + ksl) * 64 + mt2 * 32 + lane];
#pragma unroll
                for (int ksl = 0; ksl < 3; ++ksl)
#pragma unroll
                    for (int nt = 0; nt < 4; ++nt) {
                        const uint2 bv = *(const uint2*)(bs + ((kb0 + ksl) * 256 + nt * 64 + lane * 2));
                        mma16816(d[nt], a[ksl], bv);
                    }
            }

            // ---- epilogues woven into the stream ----
            if (c == 15 || c == NCHT - 1) {
                const int isL1 = (c == 15);
                // write own D partials
#pragma unroll
                for (int nt = 0; nt < 4; ++nt) {
                    const int row = mt2 * 16 + gid;
                    const int col = nt * 8 + tig * 2;
                    red[(kh * 32 + row) * 33 + col]         = d[nt][0];
                    red[(kh * 32 + row) * 33 + col + 1]     = d[nt][1];
                    red[(kh * 32 + row + 8) * 33 + col]     = d[nt][2];
                    red[(kh * 32 + row + 8) * 33 + col + 1] = d[nt][3];
                }
                __syncthreads();
                if (tid < 128) {
                    float* cs = isL1 ? c2s : c1s;
                    float (*bias)[4] = isL1 ? bias1 : bias0;
                    const int wp = isL1 ? pr : p2;
                    unsigned* imh = isL1 ? g_Bh2[0][wp] : g_Bh1[0][wp];
                    unsigned* iml = isL1 ? g_Bh2[1][wp] : g_Bh1[1][wp];
                    float hv[2];
#pragma unroll
                    for (int w = 0; w < 2; ++w) {
                        const int j = 2 * vp + w;
                        float s[4];
#pragma unroll
                        for (int g = 0; g < 4; ++g) {
                            float acc = bias[w][g];
#pragma unroll
                            for (int k4 = 0; k4 < 4; ++k4)
                                acc += red[(k4 * 32 + j * 4 + g) * 33 + np];
                            s[g] = acc;
                        }
                        const float ig = sigm(s[0]), fg = sigm(s[1]);
                        const float gv = tanh_fast(s[2]), og = sigm(s[3]);
                        cs[w] = fg * cs[w] + ig * gv;
                        hv[w] = og * tanh_fast(cs[w]);
                        if (isL1 && i == TT) g_h2f[n * HH + m * 8 + j] = hv[w];
                    }
                    const unsigned ph = pack_bf16(hv[0], hv[1]);
                    const float l0 = hv[0] - __bfloat162float(__float2bfloat16(hv[0]));
                    const float l1 = hv[1] - __bfloat162float(__float2bfloat16(hv[1]));
                    const unsigned pl = pack_bf16(l0, l1);
                    const int qg = m * 4 + vp;   // global unit-pair
                    const int idx = (qg >> 3) * 512 + (n >> 3) * 64 + (n & 7) * 8
                                  + (qg & 3) * 2 + ((qg >> 2) & 1);
                    imh[idx] = ph;
                    iml[idx] = pl;
                }
                // reset accumulators for the next phase
#pragma unroll
                for (int a = 0; a < 4; ++a)
#pragma unroll
                    for (int b = 0; b < 4; ++b) d[a][b] = 0.f;
            }
        }
        gbar(++bctr * NCTA);
    }

    // FC head on h2(511)
    if (cta == 0) {
        const int b = tid >> 2, jq = tid & 3;
        float a = 0.f;
        for (int j = jq * 128; j < jq * 128 + 128; ++j)
            a = fmaf(g_h2f[b * HH + j], fcw[j], a);
        a += __shfl_xor_sync(0xFFFFFFFFu, a, 1);
        a += __shfl_xor_sync(0xFFFFFFFFu, a, 2);
        if (jq == 0) out[b] = a + fcb[0];
    }
}

extern "C" void kernel_launch(void* const* d_in, const int* in_sizes, int n_in,
                              void* d_out, int out_size) {
    (void)in_sizes; (void)n_in; (void)out_size;
    const float* x    = (const float*)d_in[0];
    const float* Wih0 = (const float*)d_in[1];
    const float* Whh0 = (const float*)d_in[2];
    const float* bih0 = (const float*)d_in[3];
    const float* bhh0 = (const float*)d_in[4];
    const float* Wih1 = (const float*)d_in[5];
    const float* Whh1 = (const float*)d_in[6];
    const float* bih1 = (const float*)d_in[7];
    const float* bhh1 = (const float*)d_in[8];
    const float* fcw  = (const float*)d_in[9];
    const float* fcb  = (const float*)d_in[10];
    float* out = (float*)d_out;

    cudaFuncSetAttribute(lstm_mma_kernel, cudaFuncAttributeMaxDynamicSharedMemorySize, SM_TOTAL);

    prep_kernel<<<512, 256>>>(x, Wih0, Whh0, Wih1, Whh1);
    lstm_mma_kernel<<<NCTA, NTHR, SM_TOTAL>>>(bih0, bhh0, bih1, bhh1, fcw, fcb, out);
}

// round 10
// speedup vs baseline: 3.8138x; 1.4376x over previous
#include <cuda_runtime.h>
#include <cuda_fp16.h>
#include <stdint.h>

#define TT   512
#define HH   512
#define DIN  64
#define NCTA 128
#define NTHR 256
#define NB1  64           // L1 B-ksteps (K=1024 / 16)
#define NB0  36           // L0 B-ksteps (K=576 / 16)
#define NCHT 25           // 16 L1 chunks + 9 L0 chunks, 4 B-ksteps each
#define RING 8
#define LOOK 6
#define CBYTES 4096       // 4 ks * 32 batch * 16 k * 2B
#define SM_RED  32768
#define SM_TBL  49664
#define SM_TOTAL 50464

// ---- persistent device globals (no cudaMalloc allowed) ----
__device__ uint4    g_A0[64 * NB0 * 2 * 64];        // 4.5 MB  L0 A-fragments [tile][bks][term][frag]
__device__ uint4    g_A1[64 * NB1 * 2 * 64];        // 8.0 MB  L1 A-fragments
__device__ unsigned g_Bx[TT * 2048];                // x B-fragments (fp16 hi)
__device__ unsigned g_Bh1[2][32 * 512];             // h1 B-image [parity]
__device__ unsigned g_Bh2[2][32 * 512];             // h2 B-image [parity]
__device__ float    g_h2f[64 * HH];
__device__ unsigned g_bar;

__device__ __forceinline__ float sigm(float x)      { return 1.f / (1.f + __expf(-x)); }
__device__ __forceinline__ float tanh_fast(float x) { return 2.f / (1.f + __expf(-2.f * x)) - 1.f; }

__device__ __forceinline__ uint32_t smem_u32(const void* p) {
    uint32_t a;
    asm("{ .reg .u64 t; cvta.to.shared.u64 t, %1; cvt.u32.u64 %0, t; }" : "=r"(a) : "l"(p));
    return a;
}
__device__ __forceinline__ void mma16816(float* d, const uint4 a, const uint2 b) {
    asm volatile(
        "mma.sync.aligned.m16n8k16.row.col.f32.f16.f16.f32 "
        "{%0,%1,%2,%3}, {%4,%5,%6,%7}, {%8,%9}, {%0,%1,%2,%3};"
        : "+f"(d[0]), "+f"(d[1]), "+f"(d[2]), "+f"(d[3])
        : "r"(a.x), "r"(a.y), "r"(a.z), "r"(a.w), "r"(b.x), "r"(b.y));
}
__device__ __forceinline__ unsigned pack_h2(float a, float b) {
    __half2 h = __floats2half2_rn(a, b);
    return *(unsigned*)&h;
}

// ---- prep: zero parity-1 state + A weights (hi/lo fp16 fragments) + x fragments ----
#define NA0U (64 * NB0 * 2 * 64)
#define NAU  (64 * NB0 * 2 * 64 + 64 * NB1 * 2 * 64)
#define NXU  (TT * 2048)

__global__ void prep_kernel(const float* __restrict__ x,
                            const float* __restrict__ Wih0, const float* __restrict__ Whh0,
                            const float* __restrict__ Wih1, const float* __restrict__ Whh1) {
    const int gtid = blockIdx.x * blockDim.x + threadIdx.x;
    if (gtid == 0) g_bar = 0u;
    for (int i = gtid; i < 32 * 512; i += gridDim.x * blockDim.x) {
        g_Bh1[1][i] = 0u; g_Bh2[1][i] = 0u;
    }
    for (int i = gtid; i < NAU; i += gridDim.x * blockDim.x) {
        const int isA1 = (i >= NA0U);
        const int i4 = isA1 ? i - NA0U : i;
        const int NB = isA1 ? NB1 : NB0;
        const int lane = i4 & 31, mt = (i4 >> 5) & 1, term = (i4 >> 6) & 1;
        const int r2 = i4 >> 7;
        const int bks = r2 % NB, tile = r2 / NB;
        const int gid = lane >> 2, tig = lane & 3;
        unsigned vals[4];
#pragma unroll
        for (int ri = 0; ri < 4; ++ri) {
            const int rl = mt * 16 + gid + ((ri & 1) * 8);
            const int k  = bks * 16 + tig * 2 + ((ri & 2) ? 8 : 0);
            const int rg = (rl & 3) * HH + tile * 8 + (rl >> 2);
            float v0, v1;
            if (isA1) {
                v0 = (k < 512) ? Wih1[rg * HH + k]     : Whh1[rg * HH + k - 512];
                v1 = (k < 512) ? Wih1[rg * HH + k + 1] : Whh1[rg * HH + k + 1 - 512];
            } else {
                v0 = (k     < 512) ? Whh0[rg * HH + k]     : Wih0[rg * DIN + k - 512];
                v1 = (k + 1 < 512) ? Whh0[rg * HH + k + 1] : Wih0[rg * DIN + k + 1 - 512];
            }
            if (term) {
                v0 -= __half2float(__float2half_rn(v0));
                v1 -= __half2float(__float2half_rn(v1));
            }
            vals[ri] = pack_h2(v0, v1);
        }
        uint4 o; o.x = vals[0]; o.y = vals[1]; o.z = vals[2]; o.w = vals[3];
        if (isA1) g_A1[i4] = o; else g_A0[i4] = o;
    }
    for (int j = gtid; j < NXU; j += gridDim.x * blockDim.x) {
        const int t = j >> 11, e = j & 2047;
        const int reg = e & 1, lane = (e >> 1) & 31, ntl = (e >> 6) & 7, ksx = e >> 9;
        const int nb = ntl * 8 + (lane >> 2);
        const int kx = ksx * 16 + (lane & 3) * 2 + reg * 8;
        g_Bx[j] = pack_h2(x[(nb * TT + t) * DIN + kx], x[(nb * TT + t) * DIN + kx + 1]);
    }
}

// acq/rel grid barrier — no membar.gl, so no L1D flush (CCTL.IVALL).
__device__ __forceinline__ void gbar(unsigned target) {
    __syncthreads();
    if (threadIdx.x == 0) {
        unsigned v;
        asm volatile("atom.release.gpu.global.add.u32 %0, [%1], %2;"
                     : "=r"(v) : "l"(&g_bar), "r"(1u) : "memory");
        do {
            asm volatile("ld.acquire.gpu.global.u32 %0, [%1];"
                         : "=r"(v) : "l"(&g_bar) : "memory");
        } while (v < target);
    }
    __syncthreads();
}

__global__ void __launch_bounds__(NTHR, 1) lstm_mma_kernel(
    const float* __restrict__ bih0, const float* __restrict__ bhh0,
    const float* __restrict__ bih1, const float* __restrict__ bhh1,
    const float* __restrict__ fcw,  const float* __restrict__ fcb,
    float* __restrict__ out)
{
    extern __shared__ char smem[];
    const uint32_t sbase = smem_u32(smem);
    float* red = (float*)(smem + SM_RED);             // [kh 4][row 32][pitch 33]
    uint64_t* tbl = (uint64_t*)(smem + SM_TBL);       // 100 B-kstep source entries

    const int tid = threadIdx.x;
    const int lane = tid & 31, wid = tid >> 5;
    const int gid = lane >> 2, tig = lane & 3;
    const int cta = blockIdx.x;
    const int nh2 = cta >> 6;                // batch half
    const int m = cta & 63;                  // M32 tile (both layers)
    const int mt2 = wid & 1, kh = wid >> 1;  // warps = mt2(2) x kh(4)
    const uint4* Ab1 = g_A1 + (size_t)m * (NB1 * 128);
    const uint4* Ab0 = g_A0 + (size_t)m * (NB0 * 128);

    // Build B-kstep source table: base pointer | type (0=h1,1=h2,2=x)
    for (int ks = tid; ks < 100; ks += NTHR) {
        uint64_t base; int ty;
        if (ks < 64) {
            if (ks < 32) { base = (uint64_t)&g_Bh1[0][ks * 512];        ty = 0; }
            else         { base = (uint64_t)&g_Bh2[0][(ks - 32) * 512]; ty = 1; }
        } else {
            const int ke = ks - 64;
            if (ke < 32) { base = (uint64_t)&g_Bh1[0][ke * 512];        ty = 0; }
            else         { base = (uint64_t)&g_Bx[(ke - 32) * 512];     ty = 2; }
        }
        tbl[ks] = base | (uint64_t)ty;
    }

    // epilogue mapping (threads 0..127): vp = unit pair, np = batch-local
    const int np = tid & 31, vp = tid >> 5;
    const int n = nh2 * 32 + np;
    float bias0[2][4], bias1[2][4], c1s[2] = {0.f, 0.f}, c2s[2] = {0.f, 0.f};
    if (tid < 128) {
#pragma unroll
        for (int w = 0; w < 2; ++w) {
            const int jj = m * 8 + 2 * vp + w;
#pragma unroll
            for (int g = 0; g < 4; ++g) {
                bias0[w][g] = bih0[g * HH + jj] + bhh0[g * HH + jj];
                bias1[w][g] = bih1[g * HH + jj] + bhh1[g * HH + jj];
            }
        }
    }
    __syncthreads();   // table visible

    float d[4][4];
#pragma unroll
    for (int a = 0; a < 4; ++a)
#pragma unroll
        for (int b = 0; b < 4; ++b) d[a][b] = 0.f;

    unsigned bctr = 0;
    for (int i = 0; i <= TT; ++i) {
        const int pr = (i + 1) & 1;          // h1(i-1) parity
        const int p2 = i & 1;                // h2 read parity / h1 write parity
        const uint32_t prOff = pr << 16, p2Off = p2 << 16, tOff = i << 13;
        const int clo = (i == 0) ? 16 : 0;
        const int chi = (i == TT) ? 16 : NCHT;

        // ---- staging: one cp.async per thread per chunk ----
        #define STAGE(cc_) do {                                                   \
            const int cc = (cc_);                                                 \
            if (cc < chi) {                                                       \
                const int kbase = (cc < 16) ? cc * 4 : 64 + (cc - 16) * 4;        \
                const uint64_t raw = tbl[kbase + (tid >> 6)];                     \
                const int ty = (int)(raw & 3);                                    \
                const char* bp = (const char*)(raw & ~3ull);                      \
                const uint32_t add = (ty == 0) ? prOff : (ty == 1) ? p2Off : tOff;\
                const char* src = bp + add + nh2 * 1024 + (tid & 63) * 16;        \
                asm volatile("cp.async.cg.shared.global [%0], [%1], 16;"          \
                             :: "r"(sbase + (cc & 7) * CBYTES + tid * 16),        \
                                "l"(src) : "memory");                             \
            }                                                                     \
            asm volatile("cp.async.commit_group;" ::: "memory");                  \
        } while (0)

        #define PREFA(areg_, cc_) do {                                            \
            const int cc = (cc_);                                                 \
            if (cc < chi) {                                                       \
                const uint4* Ab; int bks;                                         \
                if (cc < 16) { Ab = Ab1; bks = cc * 4 + kh; }                     \
                else         { Ab = Ab0; bks = (cc - 16) * 4 + kh; }              \
                areg_[0] = Ab[(bks * 2 + 0) * 64 + mt2 * 32 + lane];              \
                areg_[1] = Ab[(bks * 2 + 1) * 64 + mt2 * 32 + lane];              \
            }                                                                     \
        } while (0)

        uint4 acur[2];
        PREFA(acur, clo);
#pragma unroll
        for (int j = 0; j < LOOK; ++j) STAGE(clo + j);

        for (int c = clo; c < chi; ++c) {
            STAGE(c + LOOK);
            uint4 anxt[2];
            PREFA(anxt, c + 1);
            asm volatile("cp.async.wait_group %0;" :: "n"(LOOK) : "memory");
            __syncthreads();

            // MMA: this warp's B-kstep (kh) of chunk c; hi+lo A terms share B
            {
                const uint32_t* bs = (const uint32_t*)(smem + (c & 7) * CBYTES);
#pragma unroll
                for (int nt = 0; nt < 4; ++nt) {
                    const uint2 bv = *(const uint2*)(bs + kh * 256 + nt * 64 + lane * 2);
                    mma16816(d[nt], acur[0], bv);
                    mma16816(d[nt], acur[1], bv);
                }
            }

            if (c == 15 || c == NCHT - 1) {
                const int isL1 = (c == 15);
#pragma unroll
                for (int nt = 0; nt < 4; ++nt) {
                    const int row = mt2 * 16 + gid;
                    const int col = nt * 8 + tig * 2;
                    red[(kh * 32 + row) * 33 + col]         = d[nt][0];
                    red[(kh * 32 + row) * 33 + col + 1]     = d[nt][1];
                    red[(kh * 32 + row + 8) * 33 + col]     = d[nt][2];
                    red[(kh * 32 + row + 8) * 33 + col + 1] = d[nt][3];
                }
                __syncthreads();
                if (tid < 128) {
                    float* cs = isL1 ? c2s : c1s;
                    float (*bias)[4] = isL1 ? bias1 : bias0;
                    const int wp = isL1 ? pr : p2;
                    unsigned* imh = isL1 ? g_Bh2[wp] : g_Bh1[wp];
                    float hv[2];
#pragma unroll
                    for (int w = 0; w < 2; ++w) {
                        const int j = 2 * vp + w;
                        float s[4];
#pragma unroll
                        for (int g = 0; g < 4; ++g) {
                            float acc = bias[w][g];
#pragma unroll
                            for (int k4 = 0; k4 < 4; ++k4)
                                acc += red[(k4 * 32 + j * 4 + g) * 33 + np];
                            s[g] = acc;
                        }
                        const float ig = sigm(s[0]), fg = sigm(s[1]);
                        const float gv = tanh_fast(s[2]), og = sigm(s[3]);
                        cs[w] = fg * cs[w] + ig * gv;
                        hv[w] = og * tanh_fast(cs[w]);
                        if (isL1 && i == TT) g_h2f[n * HH + m * 8 + j] = hv[w];
                    }
                    const int qg = m * 4 + vp;
                    const int idx = (qg >> 3) * 512 + (n >> 3) * 64 + (n & 7) * 8
                                  + (qg & 3) * 2 + ((qg >> 2) & 1);
                    imh[idx] = pack_h2(hv[0], hv[1]);
                }
#pragma unroll
                for (int a = 0; a < 4; ++a)
#pragma unroll
                    for (int b = 0; b < 4; ++b) d[a][b] = 0.f;
            }
            acur[0] = anxt[0];
            acur[1] = anxt[1];
        }
        #undef STAGE
        #undef PREFA
        gbar(++bctr * NCTA);
    }

    // FC head on h2(511)
    if (cta == 0) {
        const int b = tid >> 2, jq = tid & 3;
        float a = 0.f;
        for (int j = jq * 128; j < jq * 128 + 128; ++j)
            a = fmaf(g_h2f[b * HH + j], fcw[j], a);
        a += __shfl_xor_sync(0xFFFFFFFFu, a, 1);
        a += __shfl_xor_sync(0xFFFFFFFFu, a, 2);
        if (jq == 0) out[b] = a + fcb[0];
    }
}

extern "C" void kernel_launch(void* const* d_in, const int* in_sizes, int n_in,
                              void* d_out, int out_size) {
    (void)in_sizes; (void)n_in; (void)out_size;
    const float* x    = (const float*)d_in[0];
    const float* Wih0 = (const float*)d_in[1];
    const float* Whh0 = (const float*)d_in[2];
    const float* bih0 = (const float*)d_in[3];
    const float* bhh0 = (const float*)d_in[4];
    const float* Wih1 = (const float*)d_in[5];
    const float* Whh1 = (const float*)d_in[6];
    const float* bih1 = (const float*)d_in[7];
    const float* bhh1 = (const float*)d_in[8];
    const float* fcw  = (const float*)d_in[9];
    const float* fcb  = (const float*)d_in[10];
    float* out = (float*)d_out;

    cudaFuncSetAttribute(lstm_mma_kernel, cudaFuncAttributeMaxDynamicSharedMemorySize, SM_TOTAL);

    prep_kernel<<<512, 256>>>(x, Wih0, Whh0, Wih1, Whh1);
    lstm_mma_kernel<<<NCTA, NTHR, SM_TOTAL>>>(bih0, bhh0, bih1, bhh1, fcw, fcb, out);
}